// round 13
// baseline (speedup 1.0000x reference)
#include <cuda_runtime.h>
#include <cuda_bf16.h>
#include <cuda_fp16.h>
#include <cstdint>

#define Hh 128
#define Ww 128
#define Cc 64
#define Oo 64
#define KK 9
#define Bb 4
#define HW (Hh * Ww)
#define NT 256                   // threads per block

#define SPAD 130                 // fallback s tile row stride
#define OSTRIDE 132              // fallback epilogue staging stride

// ---------------- scratch (no allocs allowed) ----------------
__device__ __half g_xh[(size_t)Bb * HW * Cc];       // NHWC fp16 image
__device__ float  g_wt[KK * Cc * Oo];               // fallback: [t][c][o]
__device__ uint4  g_wh[KK * 512];                   // per-tap B tile [o=64][c=64] fp16, SW128 pre-swizzled

// Is the current device-compile pass feature-complete sm_103a?
#if defined(__CUDA_ARCH__) && (defined(__CUDA_ARCH_FEAT_SM103_ALL) || defined(__CUDA_ARCH_FEAT_SM100_ALL))
#define HAS_TCGEN05 1
#else
#define HAS_TCGEN05 0
#endif

__device__ __forceinline__ uint32_t sw128(uint32_t off) { return off ^ ((off >> 3) & 0x70); }

// ---------------------------------------------------------------------------
// x: [b][c][y][x] -> g_xh (fp16 NHWC). 512 blocks x 256 thr, one (b,y) row
// (full 64 channels) per block. float4 reads, uint4 (8-ch fp16) writes.
// ---------------------------------------------------------------------------
__global__ __launch_bounds__(256) void transpose_x_kernel(const float* __restrict__ x) {
    __shared__ float tile[64][129];
    int blk = blockIdx.x;                // b*128 + y
    int b = blk >> 7, y = blk & 127;
    const float* src = x + (size_t)b * Cc * HW + (size_t)y * Ww;
    int t = threadIdx.x;
    // reads: 64 c * 32 x4-groups = 2048 float4 tasks, 8 iters
#pragma unroll
    for (int k = 0; k < 8; ++k) {
        int i = t + k * 256;
        int c = i >> 5, x4 = i & 31;
        float4 v = *(const float4*)(src + (size_t)c * HW + x4 * 4);
        tile[c][x4 * 4 + 0] = v.x; tile[c][x4 * 4 + 1] = v.y;
        tile[c][x4 * 4 + 2] = v.z; tile[c][x4 * 4 + 3] = v.w;
    }
    __syncthreads();
    __half* dsth = g_xh + ((size_t)(b * Hh + y) * Ww) * Cc;
    // writes: 128 px * 8 c8-groups = 1024 uint4 tasks, 4 iters
#pragma unroll
    for (int k = 0; k < 4; ++k) {
        int i = t + k * 256;
        int xx = i >> 3, c8 = i & 7;
        int c0 = c8 * 8;
        __half2 h01 = __floats2half2_rn(tile[c0 + 0][xx], tile[c0 + 1][xx]);
        __half2 h23 = __floats2half2_rn(tile[c0 + 2][xx], tile[c0 + 3][xx]);
        __half2 h45 = __floats2half2_rn(tile[c0 + 4][xx], tile[c0 + 5][xx]);
        __half2 h67 = __floats2half2_rn(tile[c0 + 6][xx], tile[c0 + 7][xx]);
        *(uint4*)(dsth + (size_t)xx * Cc + c0) =
            make_uint4(*(uint32_t*)&h01, *(uint32_t*)&h23,
                       *(uint32_t*)&h45, *(uint32_t*)&h67);
    }
}

// ---------------------------------------------------------------------------
// weight prep: fallback [t][c][o] AND fp16 SW128 B tiles ([o][c], 128B/row)
// ---------------------------------------------------------------------------
__global__ void prep_w_kernel(const float* __restrict__ w) {
    int i = blockIdx.x * blockDim.x + threadIdx.x;
    if (i >= KK * 4096) return;
    int t = i >> 12, r = i & 4095;
    int o = r >> 6, c = r & 63;
    float val = w[(o * Cc + c) * KK + t];
    g_wt[t * 4096 + c * 64 + o] = val;                 // fallback layout
    uint32_t off = (uint32_t)(o * 128 + c * 2);        // bytes within tile
    uint32_t sw = sw128(off) >> 1;                     // uint16 index
    ((unsigned short*)g_wh)[t * 4096 + sw] = __half_as_ushort(__float2half_rn(val));
}

// packed f32x2 FMA: d = a*b + d
#define FMA2(d, a, b) asm("fma.rn.f32x2 %0, %1, %2, %0;" : "+l"(d) : "l"(a), "l"(b))

#if HAS_TCGEN05
// ---------------- tcgen05 helpers (only in feature-complete pass) ----------
__device__ __forceinline__ uint32_t smem_u32(const void* p) {
    uint32_t a;
    asm("{ .reg .u64 t; cvta.to.shared.u64 t, %1; cvt.u32.u64 %0, t; }" : "=r"(a) : "l"(p));
    return a;
}
__device__ __forceinline__ void mbar_init(uint32_t mbar, uint32_t cnt) {
    asm volatile("mbarrier.init.shared.b64 [%0], %1;" :: "r"(mbar), "r"(cnt) : "memory");
}
__device__ __forceinline__ void mbar_wait(uint32_t mbar, uint32_t parity) {
    asm volatile(
        "{\n\t.reg .pred P;\n\t"
        "WL_%=:\n\t"
        "mbarrier.try_wait.parity.acquire.cta.shared::cta.b64 P, [%0], %1, 0x989680;\n\t"
        "@!P bra WL_%=;\n\t}"
        :: "r"(mbar), "r"(parity) : "memory");
}
#define TMEM_ALLOC(sptr, ncols) \
    asm volatile("tcgen05.alloc.cta_group::1.sync.aligned.shared::cta.b32 [%0], %1;" \
                 :: "r"(sptr), "r"(ncols) : "memory")
#define TMEM_RELINQ() \
    asm volatile("tcgen05.relinquish_alloc_permit.cta_group::1.sync.aligned;")
#define TMEM_DEALLOC(taddr, ncols) \
    asm volatile("tcgen05.dealloc.cta_group::1.sync.aligned.b32 %0, %1;" :: "r"(taddr), "r"(ncols))
#define TC_COMMIT(mbar) \
    asm volatile("tcgen05.commit.cta_group::1.mbarrier::arrive::one.shared::cluster.b64 [%0];" \
                 :: "r"(mbar) : "memory")
#define TC_FENCE_AFTER()  asm volatile("tcgen05.fence::after_thread_sync;" ::: "memory")
#define TC_FENCE_BEFORE() asm volatile("tcgen05.fence::before_thread_sync;" ::: "memory")
#define FENCE_ASYNC_SHARED() asm volatile("fence.proxy.async.shared::cta;" ::: "memory")
#define TC_WAIT_LD() asm volatile("tcgen05.wait::ld.sync.aligned;" ::: "memory")

#define TCGEN05_MMA_F16(d_tmem, a_desc, b_desc, idesc, en) do {                          \
    unsigned _e = (en);                                                                  \
    asm volatile("{\n\t.reg .pred p;\n\tsetp.ne.u32 p, %4, 0;\n\t"                       \
        "tcgen05.mma.cta_group::1.kind::f16 [%0], %1, %2, %3, {%5, %5, %5, %5}, p;\n\t}" \
        :: "r"(d_tmem), "l"(a_desc), "l"(b_desc), "r"(idesc), "r"(_e), "r"(0u)           \
        : "memory");                                                                     \
} while (0)

// 16-register TMEM load (keeps epilogue under the 64-reg cap at occ 4)
#define TC_LD_X16(r, taddr)                                                              \
    asm volatile("tcgen05.ld.sync.aligned.32x32b.x16.b32 "                               \
        "{%0,%1,%2,%3,%4,%5,%6,%7,%8,%9,%10,%11,%12,%13,%14,%15}, [%16];"                \
        : "=r"((r)[0]), "=r"((r)[1]), "=r"((r)[2]), "=r"((r)[3]),                        \
          "=r"((r)[4]), "=r"((r)[5]), "=r"((r)[6]), "=r"((r)[7]),                        \
          "=r"((r)[8]), "=r"((r)[9]), "=r"((r)[10]), "=r"((r)[11]),                      \
          "=r"((r)[12]), "=r"((r)[13]), "=r"((r)[14]), "=r"((r)[15])                     \
        : "r"(taddr))

// SW128 descriptor (proven): LBO=1, SBO=64, layout=2, version=1
static __device__ __forceinline__ uint64_t make_desc128(uint32_t addr) {
    const uint64_t base = (uint64_t(2) << 61) | (uint64_t(1) << 46)
                        | (uint64_t(64) << 32) | (uint64_t(1) << 16);
    return base | ((uint64_t)(addr >> 4) & 0x3FFF);
}
// idesc kind::f16 (fp16 in, fp32 acc): dtype=F32(1)<<4, atype=F16(0), btype=F16(0),
// N/8=8 <<17, M/16=8 <<24  -> M=128, N=64
#define IDESC_F16 0x8100010u
#endif  // HAS_TCGEN05

// tcgen05 smem layout (bytes): two buffers, each A(16K) | B(8K); 52.3KB -> occ 4
#define BUF_STRIDE 24576
#define A_OFF  0
#define B_OFF  16384
#define S_W4   49152
#define S_IX   51200
#define S_TPTR 53248
#define S_MBAR0 53256
#define S_MBAR1 53264
#define SMEM_TC 53280
#define SMEM_FB 103456          // fallback layout size

// ---------------------------------------------------------------------------
// Main kernel: one (b,y) row per block, 256 threads, occupancy 4. Dual-path.
// (byte-identical to the 41.4us round-12 version)
// ---------------------------------------------------------------------------
__global__ __launch_bounds__(NT, 4) void deform_main(
    const float* __restrict__ offset,
    const float* __restrict__ bias,
    float* __restrict__ out)
{
    extern __shared__ char smc[];
    const int tid = threadIdx.x;
    const int bid = blockIdx.x;
    const int b = bid >> 7, y = bid & 127;
    const float* offb = offset + (size_t)b * (2 * KK) * HW + (size_t)y * Ww;
    const __half* xh = g_xh + (size_t)b * HW * Cc;

#if HAS_TCGEN05
    // ============ tcgen05 fp16, double-buffered, occ 4 single wave ============
    const uint32_t sbase = smem_u32(smc);
    float* s_w4 = (float*)(smc + S_W4);
    int*   s_ix = (int*)(smc + S_IX);
    const int wid = tid >> 5, lid = tid & 31;

    if (wid == 0) { TMEM_ALLOC(sbase + S_TPTR, 64); TMEM_RELINQ(); }
    if (tid == 0) { mbar_init(sbase + S_MBAR0, 1); mbar_init(sbase + S_MBAR1, 1); }
    __syncthreads();
    uint32_t tmem;
    asm volatile("ld.shared.b32 %0, [%1];" : "=r"(tmem) : "r"(sbase + S_TPTR));

    // offset prefetch (tap 0)
    float oxc = 0.f, oyc = 0.f;
    if (tid < 128) { oxc = offb[tid]; oyc = offb[HW + tid]; }

    int ph0 = 0, ph1 = 0;
    for (int t = 0; t < KK; ++t) {
        const int buf = t & 1;
        const uint32_t bufo = buf * BUF_STRIDE;
        const uint32_t mb = sbase + (buf ? S_MBAR1 : S_MBAR0);
        if (t >= 2) {   // buffer reused: wait for tap t-2's MMAs to complete
            if (buf == 0) { mbar_wait(mb, ph0); ph0 ^= 1; }
            else          { mbar_wait(mb, ph1); ph1 ^= 1; }
        }

        // ---- coords for 128 pixels; prefetch next tap's offsets ----
        if (tid < 128) {
            int xx = tid;
            float oxn = 0.f, oyn = 0.f;
            if (t + 1 < KK) {
                oxn = offb[(size_t)(2 * t + 2) * HW + xx];
                oyn = offb[(size_t)(2 * t + 3) * HW + xx];
            }
            float pxf = (float)xx + oxc, pyf = (float)y + oyc;
            float x0f = floorf(pxf), y0f = floorf(pyf);
            float fx = pxf - x0f, fy = pyf - y0f;
            int x0 = (int)x0f, y0 = (int)y0f;
            int x1 = x0 + 1,   y1 = y0 + 1;
            float vx0 = (x0 >= 0 && x0 < Ww) ? 1.f : 0.f;
            float vx1 = (x1 >= 0 && x1 < Ww) ? 1.f : 0.f;
            float vy0 = (y0 >= 0 && y0 < Hh) ? 1.f : 0.f;
            float vy1 = (y1 >= 0 && y1 < Hh) ? 1.f : 0.f;
            int cx0 = min(max(x0, 0), Ww - 1), cx1 = min(max(x1, 0), Ww - 1);
            int cy0 = min(max(y0, 0), Hh - 1), cy1 = min(max(y1, 0), Hh - 1);
            s_w4[xx * 4 + 0] = (1.f - fx) * (1.f - fy) * vx0 * vy0;
            s_w4[xx * 4 + 1] = fx * (1.f - fy) * vx1 * vy0;
            s_w4[xx * 4 + 2] = (1.f - fx) * fy * vx0 * vy1;
            s_w4[xx * 4 + 3] = fx * fy * vx1 * vy1;
            s_ix[xx * 4 + 0] = cy0 * Ww + cx0;
            s_ix[xx * 4 + 1] = cy0 * Ww + cx1;
            s_ix[xx * 4 + 2] = cy1 * Ww + cx0;
            s_ix[xx * 4 + 3] = cy1 * Ww + cx1;
            oxc = oxn; oyc = oyn;
        }
        {   // stage pre-swizzled fp16 B tile: 512 uint4 (2 iters)
            const uint4* sh = g_wh + t * 512;
            uint4* dh = (uint4*)(smc + bufo + B_OFF);
            dh[tid] = sh[tid];
            dh[tid + 256] = sh[tid + 256];
        }
        __syncthreads();

        // ---- gather (fp16, 16B per corner) + bilinear fp32 -> fp16 A tile ----
        // tasks: 128 px * 8 groups of 8 channels = 1024 = 4 x 256
        char* aP = smc + bufo + A_OFF;
#pragma unroll
        for (int it = 0; it < 4; ++it) {
            int task = it * NT + tid;
            int gpx = task >> 3, cg = task & 7;
            float w0 = s_w4[gpx * 4 + 0], w1 = s_w4[gpx * 4 + 1];
            float w2 = s_w4[gpx * 4 + 2], w3 = s_w4[gpx * 4 + 3];
            int i0 = s_ix[gpx * 4 + 0], i1 = s_ix[gpx * 4 + 1];
            int i2 = s_ix[gpx * 4 + 2], i3 = s_ix[gpx * 4 + 3];
            const int co = cg * 8;
            uint4 q0 = *(const uint4*)(xh + ((size_t)i0 << 6) + co);
            uint4 q1 = *(const uint4*)(xh + ((size_t)i1 << 6) + co);
            uint4 q2 = *(const uint4*)(xh + ((size_t)i2 << 6) + co);
            uint4 q3 = *(const uint4*)(xh + ((size_t)i3 << 6) + co);
            const __half2* a0 = (const __half2*)&q0;
            const __half2* a1 = (const __half2*)&q1;
            const __half2* a2 = (const __half2*)&q2;
            const __half2* a3 = (const __half2*)&q3;
            uint32_t res[4];
#pragma unroll
            for (int j = 0; j < 4; ++j) {
                float2 f0 = __half22float2(a0[j]);
                float2 f1 = __half22float2(a1[j]);
                float2 f2 = __half22float2(a2[j]);
                float2 f3 = __half22float2(a3[j]);
                float se = fmaf(w3, f3.x, fmaf(w2, f2.x, fmaf(w1, f1.x, w0 * f0.x)));
                float so = fmaf(w3, f3.y, fmaf(w2, f2.y, fmaf(w1, f1.y, w0 * f0.y)));
                __half2 hp = __floats2half2_rn(se, so);
                res[j] = *(uint32_t*)&hp;
            }
            uint32_t sw = sw128((uint32_t)(gpx * 128 + cg * 16));
            *(uint4*)(aP + sw) = make_uint4(res[0], res[1], res[2], res[3]);
        }
        TC_FENCE_BEFORE();
        __syncthreads();

        // ---- MMAs: 4 K-chunks, single commit ----
        if (tid == 0) {
            FENCE_ASYNC_SHARED();
            TC_FENCE_AFTER();
            uint64_t aD = make_desc128(sbase + bufo + A_OFF);
            uint64_t bD = make_desc128(sbase + bufo + B_OFF);
#pragma unroll
            for (int q = 0; q < 4; ++q) {        // K chunks of 16 fp16 = +2 units
                uint64_t o2 = (uint64_t)(q * 2);
                TCGEN05_MMA_F16(tmem, aD + o2, bD + o2, IDESC_F16,
                                (t > 0 || q > 0) ? 1u : 0u);
            }
            TC_COMMIT(mb);
        }
    }

    // final commit was tap 8 -> slot 0
    mbar_wait(sbase + S_MBAR0, ph0);
    TC_FENCE_AFTER();

    if (wid < 4) {
        int px = wid * 32 + lid;
        float* outb = out + ((size_t)b * Oo * Hh + y) * Ww + px;
#pragma unroll
        for (int chunk = 0; chunk < 4; ++chunk) {     // 16 cols at a time
            uint32_t r[16];
            TC_LD_X16(r, tmem + chunk * 16);
            TC_WAIT_LD();
#pragma unroll
            for (int j = 0; j < 16; ++j) {
                int o = chunk * 16 + j;
                outb[(size_t)o * HW] = __uint_as_float(r[j]) + __ldg(bias + o);
            }
        }
        TC_FENCE_BEFORE();
    }
    __syncthreads();
    if (wid == 0) TMEM_DEALLOC(tmem, 64);

#else
    // ============ FFMA2 fallback path (fp16 image, 256 thr: 128 cons/128 prod) ============
    float* smem = (float*)smc;
    float* sms  = smem;                        // 2 x [64][SPAD]
    float* smw  = smem + 2 * 64 * SPAD;        // 2 x [64][64]
    float* smw4 = smw + 2 * 64 * 64;           // [128][4]
    int*   smix = (int*)(smw4 + 128 * 4);      // [128][4]

    const bool producer = (tid >= 128);
    const int ptid = tid - 128;
    const int px0 = (tid & 15) * 8;
    const int o0  = (tid >> 4) * 8;

    unsigned long long acc[32];                // 8 px x 4 o-pairs
#pragma unroll
    for (int i = 0; i < 32; ++i) acc[i] = 0ull;

    auto produce = [&](int tt) {
        float* sdst = sms + (tt & 1) * 64 * SPAD;
        {
            int xx = ptid;
            float ox = offb[(size_t)(2 * tt)     * HW + xx];
            float oy = offb[(size_t)(2 * tt + 1) * HW + xx];
            float pxf = (float)xx + ox;
            float pyf = (float)y  + oy;
            float x0f = floorf(pxf), y0f = floorf(pyf);
            float fx = pxf - x0f, fy = pyf - y0f;
            int x0 = (int)x0f, y0 = (int)y0f;
            int x1 = x0 + 1,   y1 = y0 + 1;
            float vx0 = (x0 >= 0 && x0 < Ww) ? 1.f : 0.f;
            float vx1 = (x1 >= 0 && x1 < Ww) ? 1.f : 0.f;
            float vy0 = (y0 >= 0 && y0 < Hh) ? 1.f : 0.f;
            float vy1 = (y1 >= 0 && y1 < Hh) ? 1.f : 0.f;
            int cx0 = min(max(x0, 0), Ww - 1), cx1 = min(max(x1, 0), Ww - 1);
            int cy0 = min(max(y0, 0), Hh - 1), cy1 = min(max(y1, 0), Hh - 1);
            smw4[xx * 4 + 0] = (1.f - fx) * (1.f - fy) * vx0 * vy0;
            smw4[xx * 4 + 1] = fx * (1.f - fy) * vx1 * vy0;
            smw4[xx * 4 + 2] = (1.f - fx) * fy * vx0 * vy1;
            smw4[xx * 4 + 3] = fx * fy * vx1 * vy1;
            smix[xx * 4 + 0] = cy0 * Ww + cx0;
            smix[xx * 4 + 1] = cy0 * Ww + cx1;
            smix[xx * 4 + 2] = cy1 * Ww + cx0;
            smix[xx * 4 + 3] = cy1 * Ww + cx1;
        }
        {
            const float4* wsrc = (const float4*)(g_wt + (size_t)tt * Cc * Oo);
            float4* wdst = (float4*)(smw + (tt & 1) * 64 * 64);
#pragma unroll
            for (int i = 0; i < 8; ++i) wdst[ptid + i * 128] = wsrc[ptid + i * 128];
        }
        asm volatile("bar.sync 1, 128;" ::: "memory");
#pragma unroll 4
        for (int it = 0; it < 16; ++it) {
            int task = it * 128 + ptid;
            int gpx = task >> 4, cg = task & 15;
            float w0 = smw4[gpx * 4 + 0], w1 = smw4[gpx * 4 + 1];
            float w2 = smw4[gpx * 4 + 2], w3 = smw4[gpx * 4 + 3];
            int i0 = smix[gpx * 4 + 0], i1 = smix[gpx * 4 + 1];
            int i2 = smix[gpx * 4 + 2], i3 = smix[gpx * 4 + 3];
            const int co = cg * 4;
            uint2 q0 = *(const uint2*)(xh + ((size_t)i0 << 6) + co);
            uint2 q1 = *(const uint2*)(xh + ((size_t)i1 << 6) + co);
            uint2 q2 = *(const uint2*)(xh + ((size_t)i2 << 6) + co);
            uint2 q3 = *(const uint2*)(xh + ((size_t)i3 << 6) + co);
            const __half2* a0 = (const __half2*)&q0;
            const __half2* a1 = (const __half2*)&q1;
            const __half2* a2 = (const __half2*)&q2;
            const __half2* a3 = (const __half2*)&q3;
            float* dc = sdst + (cg * 4) * SPAD + gpx;
#pragma unroll
            for (int j = 0; j < 2; ++j) {
                float2 f0 = __half22float2(a0[j]);
                float2 f1 = __half22float2(a1[j]);
                float2 f2 = __half22float2(a2[j]);
                float2 f3 = __half22float2(a3[j]);
                dc[(2 * j) * SPAD] =
                    fmaf(w3, f3.x, fmaf(w2, f2.x, fmaf(w1, f1.x, w0 * f0.x)));
                dc[(2 * j + 1) * SPAD] =
                    fmaf(w3, f3.y, fmaf(w2, f2.y, fmaf(w1, f1.y, w0 * f0.y)));
            }
        }
    };

    if (producer) produce(0);
    __syncthreads();

    for (int t = 0; t < KK; ++t) {
        if (producer) {
            if (t + 1 < KK) produce(t + 1);
        } else {
            const float* sb = sms + (t & 1) * 64 * SPAD + px0;
            const float* sw = smw + (t & 1) * 64 * 64 + o0;
            for (int c = 0; c < 64; ++c) {
                ulonglong2 wA = *(const ulonglong2*)(sw + c * 64);
                ulonglong2 wB = *(const ulonglong2*)(sw + c * 64 + 4);
#pragma unroll
                for (int i = 0; i < 8; ++i) {
                    float sf = sb[c * SPAD + i];
                    unsigned long long dv;
                    asm("mov.b64 %0, {%1,%1};" : "=l"(dv) : "r"(__float_as_uint(sf)));
                    FMA2(acc[i * 4 + 0], wA.x, dv);
                    FMA2(acc[i * 4 + 1], wA.y, dv);
                    FMA2(acc[i * 4 + 2], wB.x, dv);
                    FMA2(acc[i * 4 + 3], wB.y, dv);
                }
            }
        }
        __syncthreads();
    }

    if (!producer) {
        float* stg = sms;
#pragma unroll
        for (int k = 0; k < 4; ++k) {
            float blo = bias[o0 + 2 * k];
            float bhi = bias[o0 + 2 * k + 1];
#pragma unroll
            for (int i = 0; i < 8; ++i) {
                unsigned long long a = acc[i * 4 + k];
                float lo = __uint_as_float((unsigned)(a & 0xffffffffull));
                float hi = __uint_as_float((unsigned)(a >> 32));
                stg[(o0 + 2 * k) * OSTRIDE + px0 + i]     = lo + blo;
                stg[(o0 + 2 * k + 1) * OSTRIDE + px0 + i] = hi + bhi;
            }
        }
    }
    __syncthreads();
    {
        float* outb = out + ((size_t)b * Oo * Hh + y) * Ww;
        const float* stg = sms;
        for (int idx = tid; idx < Oo * Ww / 4; idx += NT) {
            int o = idx >> 5, q = idx & 31;
            float4 v = *(const float4*)(stg + o * OSTRIDE + q * 4);
            *(float4*)(outb + (size_t)o * HW + q * 4) = v;
        }
    }
#endif
}

extern "C" void kernel_launch(void* const* d_in, const int* in_sizes, int n_in,
                              void* d_out, int out_size) {
    const float* x      = (const float*)d_in[0];
    const float* offset = (const float*)d_in[1];
    const float* weight = (const float*)d_in[2];
    const float* bias   = (const float*)d_in[3];
    float* out = (float*)d_out;

    transpose_x_kernel<<<Bb * Hh, 256>>>(x);
    prep_w_kernel<<<(KK * 4096 + 255) / 256, 256>>>(weight);

    int dev = 0, major = 0;
    cudaGetDevice(&dev);
    cudaDeviceGetAttribute(&major, cudaDevAttrComputeCapabilityMajor, dev);
    int smem = (major >= 10) ? SMEM_TC : SMEM_FB;   // tcgen05 path vs fallback
    cudaFuncSetAttribute(deform_main, cudaFuncAttributeMaxDynamicSharedMemorySize,
                         SMEM_FB);
    deform_main<<<Bb * Hh, NT, smem>>>(offset, bias, out);
}

// round 14
// speedup vs baseline: 1.0385x; 1.0385x over previous
#include <cuda_runtime.h>
#include <cuda_bf16.h>
#include <cuda_fp16.h>
#include <cstdint>

#define Hh 128
#define Ww 128
#define Cc 64
#define Oo 64
#define KK 9
#define Bb 4
#define HW (Hh * Ww)
#define NT 256                   // threads per main block

#define SPAD 130                 // fallback s tile row stride
#define OSTRIDE 132              // fallback epilogue staging stride

// ---------------- scratch (no allocs allowed) ----------------
__device__ __half g_xh[(size_t)Bb * HW * Cc];       // NHWC fp16 image
__device__ float  g_wt[KK * Cc * Oo];               // fallback: [t][c][o]
__device__ uint4  g_wh[KK * 512];                   // per-tap B tile [o=64][c=64] fp16, SW128 pre-swizzled

// Is the current device-compile pass feature-complete sm_103a?
#if defined(__CUDA_ARCH__) && (defined(__CUDA_ARCH_FEAT_SM103_ALL) || defined(__CUDA_ARCH_FEAT_SM100_ALL))
#define HAS_TCGEN05 1
#else
#define HAS_TCGEN05 0
#endif

__device__ __forceinline__ uint32_t sw128(uint32_t off) { return off ^ ((off >> 3) & 0x70); }

// ---------------------------------------------------------------------------
// Fused prep kernel, 128 threads/block:
//   blocks [0, 1024):   x [b][c][y][x] -> g_xh fp16 NHWC (round-12 proven shape:
//                       tile = 32 channels x 128 px of one (b,y) row)
//   blocks [1024, 1312): weight prep (fallback layout + fp16 SW128 B tiles)
// ---------------------------------------------------------------------------
__global__ __launch_bounds__(128) void prep_kernel(const float* __restrict__ x,
                                                   const float* __restrict__ w) {
    int blk = blockIdx.x;
    int t = threadIdx.x;
    if (blk >= 1024) {
        // ---- weight prep: KK*4096 = 36864 elems over 288 blocks x 128 thr ----
        int i = (blk - 1024) * 128 + t;
        if (i < KK * 4096) {
            int tt = i >> 12, r = i & 4095;
            int o = r >> 6, c = r & 63;
            float val = w[(o * Cc + c) * KK + tt];
            g_wt[tt * 4096 + c * 64 + o] = val;            // fallback layout
            uint32_t off = (uint32_t)(o * 128 + c * 2);    // bytes within tile
            uint32_t sw = sw128(off) >> 1;                 // uint16 index
            ((unsigned short*)g_wh)[tt * 4096 + sw] =
                __half_as_ushort(__float2half_rn(val));
        }
        return;
    }
    // ---- transpose: b*256 + y*2 + half ----
    __shared__ float tile[32][129];
    int b = blk >> 8;
    int rem = blk & 255;
    int y = rem >> 1;
    int c0 = (rem & 1) * 32;
    const float* src = x + ((size_t)(b * Cc + c0)) * HW + (size_t)y * Ww;
#pragma unroll
    for (int k = 0; k < 8; ++k) {
        int i = t + k * 128;             // 32 c * 32 x4-groups
        int c = i >> 5, x4 = i & 31;
        float4 v = *(const float4*)(src + (size_t)c * HW + x4 * 4);
        tile[c][x4 * 4 + 0] = v.x; tile[c][x4 * 4 + 1] = v.y;
        tile[c][x4 * 4 + 2] = v.z; tile[c][x4 * 4 + 3] = v.w;
    }
    __syncthreads();
    __half* dsth = g_xh + ((size_t)(b * Hh + y) * Ww) * Cc + c0;
#pragma unroll
    for (int k = 0; k < 8; ++k) {
        int i = t + k * 128;             // 128 x * 8 c4-groups
        int xx = i >> 3, c4 = i & 7;
        __half2 h01 = __floats2half2_rn(tile[c4 * 4 + 0][xx], tile[c4 * 4 + 1][xx]);
        __half2 h23 = __floats2half2_rn(tile[c4 * 4 + 2][xx], tile[c4 * 4 + 3][xx]);
        *(uint2*)(dsth + (size_t)xx * Cc + c4 * 4) =
            make_uint2(*(uint32_t*)&h01, *(uint32_t*)&h23);
    }
}

// packed f32x2 FMA: d = a*b + d
#define FMA2(d, a, b) asm("fma.rn.f32x2 %0, %1, %2, %0;" : "+l"(d) : "l"(a), "l"(b))

#if HAS_TCGEN05
// ---------------- tcgen05 helpers (only in feature-complete pass) ----------
__device__ __forceinline__ uint32_t smem_u32(const void* p) {
    uint32_t a;
    asm("{ .reg .u64 t; cvta.to.shared.u64 t, %1; cvt.u32.u64 %0, t; }" : "=r"(a) : "l"(p));
    return a;
}
__device__ __forceinline__ void mbar_init(uint32_t mbar, uint32_t cnt) {
    asm volatile("mbarrier.init.shared.b64 [%0], %1;" :: "r"(mbar), "r"(cnt) : "memory");
}
__device__ __forceinline__ void mbar_wait(uint32_t mbar, uint32_t parity) {
    asm volatile(
        "{\n\t.reg .pred P;\n\t"
        "WL_%=:\n\t"
        "mbarrier.try_wait.parity.acquire.cta.shared::cta.b64 P, [%0], %1, 0x989680;\n\t"
        "@!P bra WL_%=;\n\t}"
        :: "r"(mbar), "r"(parity) : "memory");
}
#define TMEM_ALLOC(sptr, ncols) \
    asm volatile("tcgen05.alloc.cta_group::1.sync.aligned.shared::cta.b32 [%0], %1;" \
                 :: "r"(sptr), "r"(ncols) : "memory")
#define TMEM_RELINQ() \
    asm volatile("tcgen05.relinquish_alloc_permit.cta_group::1.sync.aligned;")
#define TMEM_DEALLOC(taddr, ncols) \
    asm volatile("tcgen05.dealloc.cta_group::1.sync.aligned.b32 %0, %1;" :: "r"(taddr), "r"(ncols))
#define TC_COMMIT(mbar) \
    asm volatile("tcgen05.commit.cta_group::1.mbarrier::arrive::one.shared::cluster.b64 [%0];" \
                 :: "r"(mbar) : "memory")
#define TC_FENCE_AFTER()  asm volatile("tcgen05.fence::after_thread_sync;" ::: "memory")
#define TC_FENCE_BEFORE() asm volatile("tcgen05.fence::before_thread_sync;" ::: "memory")
#define FENCE_ASYNC_SHARED() asm volatile("fence.proxy.async.shared::cta;" ::: "memory")
#define TC_WAIT_LD() asm volatile("tcgen05.wait::ld.sync.aligned;" ::: "memory")

#define TCGEN05_MMA_F16(d_tmem, a_desc, b_desc, idesc, en) do {                          \
    unsigned _e = (en);                                                                  \
    asm volatile("{\n\t.reg .pred p;\n\tsetp.ne.u32 p, %4, 0;\n\t"                       \
        "tcgen05.mma.cta_group::1.kind::f16 [%0], %1, %2, %3, {%5, %5, %5, %5}, p;\n\t}" \
        :: "r"(d_tmem), "l"(a_desc), "l"(b_desc), "r"(idesc), "r"(_e), "r"(0u)           \
        : "memory");                                                                     \
} while (0)

// 16-register TMEM load (keeps epilogue under the 64-reg cap at occ 4)
#define TC_LD_X16(r, taddr)                                                              \
    asm volatile("tcgen05.ld.sync.aligned.32x32b.x16.b32 "                               \
        "{%0,%1,%2,%3,%4,%5,%6,%7,%8,%9,%10,%11,%12,%13,%14,%15}, [%16];"                \
        : "=r"((r)[0]), "=r"((r)[1]), "=r"((r)[2]), "=r"((r)[3]),                        \
          "=r"((r)[4]), "=r"((r)[5]), "=r"((r)[6]), "=r"((r)[7]),                        \
          "=r"((r)[8]), "=r"((r)[9]), "=r"((r)[10]), "=r"((r)[11]),                      \
          "=r"((r)[12]), "=r"((r)[13]), "=r"((r)[14]), "=r"((r)[15])                     \
        : "r"(taddr))

// SW128 descriptor (proven): LBO=1, SBO=64, layout=2, version=1
static __device__ __forceinline__ uint64_t make_desc128(uint32_t addr) {
    const uint64_t base = (uint64_t(2) << 61) | (uint64_t(1) << 46)
                        | (uint64_t(64) << 32) | (uint64_t(1) << 16);
    return base | ((uint64_t)(addr >> 4) & 0x3FFF);
}
// idesc kind::f16 (fp16 in, fp32 acc): dtype=F32(1)<<4, atype=F16(0), btype=F16(0),
// N/8=8 <<17, M/16=8 <<24  -> M=128, N=64
#define IDESC_F16 0x8100010u
#endif  // HAS_TCGEN05

// tcgen05 smem layout (bytes): two buffers, each A(16K) | B(8K); 52.3KB -> occ 4
#define BUF_STRIDE 24576
#define A_OFF  0
#define B_OFF  16384
#define S_W4   49152
#define S_IX   51200
#define S_TPTR 53248
#define S_MBAR0 53256
#define S_MBAR1 53264
#define SMEM_TC 53280
#define SMEM_FB 103456          // fallback layout size

// ---------------------------------------------------------------------------
// Main kernel: one (b,y) row per block, 256 threads, occupancy 4. Dual-path.
// (byte-identical to the 41.4us round-12 version)
// ---------------------------------------------------------------------------
__global__ __launch_bounds__(NT, 4) void deform_main(
    const float* __restrict__ offset,
    const float* __restrict__ bias,
    float* __restrict__ out)
{
    extern __shared__ char smc[];
    const int tid = threadIdx.x;
    const int bid = blockIdx.x;
    const int b = bid >> 7, y = bid & 127;
    const float* offb = offset + (size_t)b * (2 * KK) * HW + (size_t)y * Ww;
    const __half* xh = g_xh + (size_t)b * HW * Cc;

#if HAS_TCGEN05
    // ============ tcgen05 fp16, double-buffered, occ 4 single wave ============
    const uint32_t sbase = smem_u32(smc);
    float* s_w4 = (float*)(smc + S_W4);
    int*   s_ix = (int*)(smc + S_IX);
    const int wid = tid >> 5, lid = tid & 31;

    if (wid == 0) { TMEM_ALLOC(sbase + S_TPTR, 64); TMEM_RELINQ(); }
    if (tid == 0) { mbar_init(sbase + S_MBAR0, 1); mbar_init(sbase + S_MBAR1, 1); }
    __syncthreads();
    uint32_t tmem;
    asm volatile("ld.shared.b32 %0, [%1];" : "=r"(tmem) : "r"(sbase + S_TPTR));

    // offset prefetch (tap 0)
    float oxc = 0.f, oyc = 0.f;
    if (tid < 128) { oxc = offb[tid]; oyc = offb[HW + tid]; }

    int ph0 = 0, ph1 = 0;
    for (int t = 0; t < KK; ++t) {
        const int buf = t & 1;
        const uint32_t bufo = buf * BUF_STRIDE;
        const uint32_t mb = sbase + (buf ? S_MBAR1 : S_MBAR0);
        if (t >= 2) {   // buffer reused: wait for tap t-2's MMAs to complete
            if (buf == 0) { mbar_wait(mb, ph0); ph0 ^= 1; }
            else          { mbar_wait(mb, ph1); ph1 ^= 1; }
        }

        // ---- coords for 128 pixels; prefetch next tap's offsets ----
        if (tid < 128) {
            int xx = tid;
            float oxn = 0.f, oyn = 0.f;
            if (t + 1 < KK) {
                oxn = offb[(size_t)(2 * t + 2) * HW + xx];
                oyn = offb[(size_t)(2 * t + 3) * HW + xx];
            }
            float pxf = (float)xx + oxc, pyf = (float)y + oyc;
            float x0f = floorf(pxf), y0f = floorf(pyf);
            float fx = pxf - x0f, fy = pyf - y0f;
            int x0 = (int)x0f, y0 = (int)y0f;
            int x1 = x0 + 1,   y1 = y0 + 1;
            float vx0 = (x0 >= 0 && x0 < Ww) ? 1.f : 0.f;
            float vx1 = (x1 >= 0 && x1 < Ww) ? 1.f : 0.f;
            float vy0 = (y0 >= 0 && y0 < Hh) ? 1.f : 0.f;
            float vy1 = (y1 >= 0 && y1 < Hh) ? 1.f : 0.f;
            int cx0 = min(max(x0, 0), Ww - 1), cx1 = min(max(x1, 0), Ww - 1);
            int cy0 = min(max(y0, 0), Hh - 1), cy1 = min(max(y1, 0), Hh - 1);
            s_w4[xx * 4 + 0] = (1.f - fx) * (1.f - fy) * vx0 * vy0;
            s_w4[xx * 4 + 1] = fx * (1.f - fy) * vx1 * vy0;
            s_w4[xx * 4 + 2] = (1.f - fx) * fy * vx0 * vy1;
            s_w4[xx * 4 + 3] = fx * fy * vx1 * vy1;
            s_ix[xx * 4 + 0] = cy0 * Ww + cx0;
            s_ix[xx * 4 + 1] = cy0 * Ww + cx1;
            s_ix[xx * 4 + 2] = cy1 * Ww + cx0;
            s_ix[xx * 4 + 3] = cy1 * Ww + cx1;
            oxc = oxn; oyc = oyn;
        }
        {   // stage pre-swizzled fp16 B tile: 512 uint4 (2 iters)
            const uint4* sh = g_wh + t * 512;
            uint4* dh = (uint4*)(smc + bufo + B_OFF);
            dh[tid] = sh[tid];
            dh[tid + 256] = sh[tid + 256];
        }
        __syncthreads();

        // ---- gather (fp16, 16B per corner) + bilinear fp32 -> fp16 A tile ----
        // tasks: 128 px * 8 groups of 8 channels = 1024 = 4 x 256
        char* aP = smc + bufo + A_OFF;
#pragma unroll
        for (int it = 0; it < 4; ++it) {
            int task = it * NT + tid;
            int gpx = task >> 3, cg = task & 7;
            float w0 = s_w4[gpx * 4 + 0], w1 = s_w4[gpx * 4 + 1];
            float w2 = s_w4[gpx * 4 + 2], w3 = s_w4[gpx * 4 + 3];
            int i0 = s_ix[gpx * 4 + 0], i1 = s_ix[gpx * 4 + 1];
            int i2 = s_ix[gpx * 4 + 2], i3 = s_ix[gpx * 4 + 3];
            const int co = cg * 8;
            uint4 q0 = *(const uint4*)(xh + ((size_t)i0 << 6) + co);
            uint4 q1 = *(const uint4*)(xh + ((size_t)i1 << 6) + co);
            uint4 q2 = *(const uint4*)(xh + ((size_t)i2 << 6) + co);
            uint4 q3 = *(const uint4*)(xh + ((size_t)i3 << 6) + co);
            const __half2* a0 = (const __half2*)&q0;
            const __half2* a1 = (const __half2*)&q1;
            const __half2* a2 = (const __half2*)&q2;
            const __half2* a3 = (const __half2*)&q3;
            uint32_t res[4];
#pragma unroll
            for (int j = 0; j < 4; ++j) {
                float2 f0 = __half22float2(a0[j]);
                float2 f1 = __half22float2(a1[j]);
                float2 f2 = __half22float2(a2[j]);
                float2 f3 = __half22float2(a3[j]);
                float se = fmaf(w3, f3.x, fmaf(w2, f2.x, fmaf(w1, f1.x, w0 * f0.x)));
                float so = fmaf(w3, f3.y, fmaf(w2, f2.y, fmaf(w1, f1.y, w0 * f0.y)));
                __half2 hp = __floats2half2_rn(se, so);
                res[j] = *(uint32_t*)&hp;
            }
            uint32_t sw = sw128((uint32_t)(gpx * 128 + cg * 16));
            *(uint4*)(aP + sw) = make_uint4(res[0], res[1], res[2], res[3]);
        }
        TC_FENCE_BEFORE();
        __syncthreads();

        // ---- MMAs: 4 K-chunks, single commit ----
        if (tid == 0) {
            FENCE_ASYNC_SHARED();
            TC_FENCE_AFTER();
            uint64_t aD = make_desc128(sbase + bufo + A_OFF);
            uint64_t bD = make_desc128(sbase + bufo + B_OFF);
#pragma unroll
            for (int q = 0; q < 4; ++q) {        // K chunks of 16 fp16 = +2 units
                uint64_t o2 = (uint64_t)(q * 2);
                TCGEN05_MMA_F16(tmem, aD + o2, bD + o2, IDESC_F16,
                                (t > 0 || q > 0) ? 1u : 0u);
            }
            TC_COMMIT(mb);
        }
    }

    // final commit was tap 8 -> slot 0
    mbar_wait(sbase + S_MBAR0, ph0);
    TC_FENCE_AFTER();

    if (wid < 4) {
        int px = wid * 32 + lid;
        float* outb = out + ((size_t)b * Oo * Hh + y) * Ww + px;
#pragma unroll
        for (int chunk = 0; chunk < 4; ++chunk) {     // 16 cols at a time
            uint32_t r[16];
            TC_LD_X16(r, tmem + chunk * 16);
            TC_WAIT_LD();
#pragma unroll
            for (int j = 0; j < 16; ++j) {
                int o = chunk * 16 + j;
                outb[(size_t)o * HW] = __uint_as_float(r[j]) + __ldg(bias + o);
            }
        }
        TC_FENCE_BEFORE();
    }
    __syncthreads();
    if (wid == 0) TMEM_DEALLOC(tmem, 64);

#else
    // ============ FFMA2 fallback path (fp16 image, 256 thr: 128 cons/128 prod) ============
    float* smem = (float*)smc;
    float* sms  = smem;                        // 2 x [64][SPAD]
    float* smw  = smem + 2 * 64 * SPAD;        // 2 x [64][64]
    float* smw4 = smw + 2 * 64 * 64;           // [128][4]
    int*   smix = (int*)(smw4 + 128 * 4);      // [128][4]

    const bool producer = (tid >= 128);
    const int ptid = tid - 128;
    const int px0 = (tid & 15) * 8;
    const int o0  = (tid >> 4) * 8;

    unsigned long long acc[32];                // 8 px x 4 o-pairs
#pragma unroll
    for (int i = 0; i < 32; ++i) acc[i] = 0ull;

    auto produce = [&](int tt) {
        float* sdst = sms + (tt & 1) * 64 * SPAD;
        {
            int xx = ptid;
            float ox = offb[(size_t)(2 * tt)     * HW + xx];
            float oy = offb[(size_t)(2 * tt + 1) * HW + xx];
            float pxf = (float)xx + ox;
            float pyf = (float)y  + oy;
            float x0f = floorf(pxf), y0f = floorf(pyf);
            float fx = pxf - x0f, fy = pyf - y0f;
            int x0 = (int)x0f, y0 = (int)y0f;
            int x1 = x0 + 1,   y1 = y0 + 1;
            float vx0 = (x0 >= 0 && x0 < Ww) ? 1.f : 0.f;
            float vx1 = (x1 >= 0 && x1 < Ww) ? 1.f : 0.f;
            float vy0 = (y0 >= 0 && y0 < Hh) ? 1.f : 0.f;
            float vy1 = (y1 >= 0 && y1 < Hh) ? 1.f : 0.f;
            int cx0 = min(max(x0, 0), Ww - 1), cx1 = min(max(x1, 0), Ww - 1);
            int cy0 = min(max(y0, 0), Hh - 1), cy1 = min(max(y1, 0), Hh - 1);
            smw4[xx * 4 + 0] = (1.f - fx) * (1.f - fy) * vx0 * vy0;
            smw4[xx * 4 + 1] = fx * (1.f - fy) * vx1 * vy0;
            smw4[xx * 4 + 2] = (1.f - fx) * fy * vx0 * vy1;
            smw4[xx * 4 + 3] = fx * fy * vx1 * vy1;
            smix[xx * 4 + 0] = cy0 * Ww + cx0;
            smix[xx * 4 + 1] = cy0 * Ww + cx1;
            smix[xx * 4 + 2] = cy1 * Ww + cx0;
            smix[xx * 4 + 3] = cy1 * Ww + cx1;
        }
        {
            const float4* wsrc = (const float4*)(g_wt + (size_t)tt * Cc * Oo);
            float4* wdst = (float4*)(smw + (tt & 1) * 64 * 64);
#pragma unroll
            for (int i = 0; i < 8; ++i) wdst[ptid + i * 128] = wsrc[ptid + i * 128];
        }
        asm volatile("bar.sync 1, 128;" ::: "memory");
#pragma unroll 4
        for (int it = 0; it < 16; ++it) {
            int task = it * 128 + ptid;
            int gpx = task >> 4, cg = task & 15;
            float w0 = smw4[gpx * 4 + 0], w1 = smw4[gpx * 4 + 1];
            float w2 = smw4[gpx * 4 + 2], w3 = smw4[gpx * 4 + 3];
            int i0 = smix[gpx * 4 + 0], i1 = smix[gpx * 4 + 1];
            int i2 = smix[gpx * 4 + 2], i3 = smix[gpx * 4 + 3];
            const int co = cg * 4;
            uint2 q0 = *(const uint2*)(xh + ((size_t)i0 << 6) + co);
            uint2 q1 = *(const uint2*)(xh + ((size_t)i1 << 6) + co);
            uint2 q2 = *(const uint2*)(xh + ((size_t)i2 << 6) + co);
            uint2 q3 = *(const uint2*)(xh + ((size_t)i3 << 6) + co);
            const __half2* a0 = (const __half2*)&q0;
            const __half2* a1 = (const __half2*)&q1;
            const __half2* a2 = (const __half2*)&q2;
            const __half2* a3 = (const __half2*)&q3;
            float* dc = sdst + (cg * 4) * SPAD + gpx;
#pragma unroll
            for (int j = 0; j < 2; ++j) {
                float2 f0 = __half22float2(a0[j]);
                float2 f1 = __half22float2(a1[j]);
                float2 f2 = __half22float2(a2[j]);
                float2 f3 = __half22float2(a3[j]);
                dc[(2 * j) * SPAD] =
                    fmaf(w3, f3.x, fmaf(w2, f2.x, fmaf(w1, f1.x, w0 * f0.x)));
                dc[(2 * j + 1) * SPAD] =
                    fmaf(w3, f3.y, fmaf(w2, f2.y, fmaf(w1, f1.y, w0 * f0.y)));
            }
        }
    };

    if (producer) produce(0);
    __syncthreads();

    for (int t = 0; t < KK; ++t) {
        if (producer) {
            if (t + 1 < KK) produce(t + 1);
        } else {
            const float* sb = sms + (t & 1) * 64 * SPAD + px0;
            const float* sw = smw + (t & 1) * 64 * 64 + o0;
            for (int c = 0; c < 64; ++c) {
                ulonglong2 wA = *(const ulonglong2*)(sw + c * 64);
                ulonglong2 wB = *(const ulonglong2*)(sw + c * 64 + 4);
#pragma unroll
                for (int i = 0; i < 8; ++i) {
                    float sf = sb[c * SPAD + i];
                    unsigned long long dv;
                    asm("mov.b64 %0, {%1,%1};" : "=l"(dv) : "r"(__float_as_uint(sf)));
                    FMA2(acc[i * 4 + 0], wA.x, dv);
                    FMA2(acc[i * 4 + 1], wA.y, dv);
                    FMA2(acc[i * 4 + 2], wB.x, dv);
                    FMA2(acc[i * 4 + 3], wB.y, dv);
                }
            }
        }
        __syncthreads();
    }

    if (!producer) {
        float* stg = sms;
#pragma unroll
        for (int k = 0; k < 4; ++k) {
            float blo = bias[o0 + 2 * k];
            float bhi = bias[o0 + 2 * k + 1];
#pragma unroll
            for (int i = 0; i < 8; ++i) {
                unsigned long long a = acc[i * 4 + k];
                float lo = __uint_as_float((unsigned)(a & 0xffffffffull));
                float hi = __uint_as_float((unsigned)(a >> 32));
                stg[(o0 + 2 * k) * OSTRIDE + px0 + i]     = lo + blo;
                stg[(o0 + 2 * k + 1) * OSTRIDE + px0 + i] = hi + bhi;
            }
        }
    }
    __syncthreads();
    {
        float* outb = out + ((size_t)b * Oo * Hh + y) * Ww;
        const float* stg = sms;
        for (int idx = tid; idx < Oo * Ww / 4; idx += NT) {
            int o = idx >> 5, q = idx & 31;
            float4 v = *(const float4*)(stg + o * OSTRIDE + q * 4);
            *(float4*)(outb + (size_t)o * HW + q * 4) = v;
        }
    }
#endif
}

extern "C" void kernel_launch(void* const* d_in, const int* in_sizes, int n_in,
                              void* d_out, int out_size) {
    const float* x      = (const float*)d_in[0];
    const float* offset = (const float*)d_in[1];
    const float* weight = (const float*)d_in[2];
    const float* bias   = (const float*)d_in[3];
    float* out = (float*)d_out;

    // fused transpose (1024 blocks) + weight prep (288 blocks)
    prep_kernel<<<1024 + 288, 128>>>(x, weight);

    int dev = 0, major = 0;
    cudaGetDevice(&dev);
    cudaDeviceGetAttribute(&major, cudaDevAttrComputeCapabilityMajor, dev);
    int smem = (major >= 10) ? SMEM_TC : SMEM_FB;   // tcgen05 path vs fallback
    cudaFuncSetAttribute(deform_main, cudaFuncAttributeMaxDynamicSharedMemorySize,
                         SMEM_FB);
    deform_main<<<Bb * Hh, NT, smem>>>(offset, bias, out);
}

// round 15
// speedup vs baseline: 1.1568x; 1.1140x over previous
#include <cuda_runtime.h>
#include <cuda_bf16.h>
#include <cuda_fp16.h>
#include <cstdint>

#define Hh 128
#define Ww 128
#define Cc 64
#define Oo 64
#define KK 9
#define Bb 4
#define HW (Hh * Ww)
#define NT 256                   // threads per main block

#define SPAD 130                 // fallback s tile row stride
#define OSTRIDE 132              // fallback epilogue staging stride

// ---------------- scratch (no allocs allowed) ----------------
__device__ __half g_xh[(size_t)Bb * HW * Cc];       // NHWC fp16 image
__device__ float  g_wt[KK * Cc * Oo];               // fallback: [t][c][o]
__device__ uint4  g_wh[KK * 512];                   // per-tap B tile [o=64][c=64] fp16, SW128 pre-swizzled

// Is the current device-compile pass feature-complete sm_103a?
#if defined(__CUDA_ARCH__) && (defined(__CUDA_ARCH_FEAT_SM103_ALL) || defined(__CUDA_ARCH_FEAT_SM100_ALL))
#define HAS_TCGEN05 1
#else
#define HAS_TCGEN05 0
#endif

__device__ __forceinline__ uint32_t sw128(uint32_t off) { return off ^ ((off >> 3) & 0x70); }

// ---------------------------------------------------------------------------
// Fused prep kernel, 128 threads/block:
//   blocks [0, 1024):   x [b][c][y][x] -> g_xh fp16 NHWC (32c x 128px tiles)
//   blocks [1024, 1312): weight prep (fallback layout + fp16 SW128 B tiles)
// ---------------------------------------------------------------------------
__global__ __launch_bounds__(128) void prep_kernel(const float* __restrict__ x,
                                                   const float* __restrict__ w) {
    int blk = blockIdx.x;
    int t = threadIdx.x;
    if (blk >= 1024) {
        int i = (blk - 1024) * 128 + t;
        if (i < KK * 4096) {
            int tt = i >> 12, r = i & 4095;
            int o = r >> 6, c = r & 63;
            float val = w[(o * Cc + c) * KK + tt];
            g_wt[tt * 4096 + c * 64 + o] = val;            // fallback layout
            uint32_t off = (uint32_t)(o * 128 + c * 2);    // bytes within tile
            uint32_t sw = sw128(off) >> 1;                 // uint16 index
            ((unsigned short*)g_wh)[tt * 4096 + sw] =
                __half_as_ushort(__float2half_rn(val));
        }
        return;
    }
    __shared__ float tile[32][129];
    int b = blk >> 8;
    int rem = blk & 255;
    int y = rem >> 1;
    int c0 = (rem & 1) * 32;
    const float* src = x + ((size_t)(b * Cc + c0)) * HW + (size_t)y * Ww;
#pragma unroll
    for (int k = 0; k < 8; ++k) {
        int i = t + k * 128;             // 32 c * 32 x4-groups
        int c = i >> 5, x4 = i & 31;
        float4 v = *(const float4*)(src + (size_t)c * HW + x4 * 4);
        tile[c][x4 * 4 + 0] = v.x; tile[c][x4 * 4 + 1] = v.y;
        tile[c][x4 * 4 + 2] = v.z; tile[c][x4 * 4 + 3] = v.w;
    }
    __syncthreads();
    __half* dsth = g_xh + ((size_t)(b * Hh + y) * Ww) * Cc + c0;
#pragma unroll
    for (int k = 0; k < 8; ++k) {
        int i = t + k * 128;             // 128 x * 8 c4-groups
        int xx = i >> 3, c4 = i & 7;
        __half2 h01 = __floats2half2_rn(tile[c4 * 4 + 0][xx], tile[c4 * 4 + 1][xx]);
        __half2 h23 = __floats2half2_rn(tile[c4 * 4 + 2][xx], tile[c4 * 4 + 3][xx]);
        *(uint2*)(dsth + (size_t)xx * Cc + c4 * 4) =
            make_uint2(*(uint32_t*)&h01, *(uint32_t*)&h23);
    }
}

// packed f32x2 FMA: d = a*b + d
#define FMA2(d, a, b) asm("fma.rn.f32x2 %0, %1, %2, %0;" : "+l"(d) : "l"(a), "l"(b))

#if HAS_TCGEN05
// ---------------- tcgen05 helpers (only in feature-complete pass) ----------
__device__ __forceinline__ uint32_t smem_u32(const void* p) {
    uint32_t a;
    asm("{ .reg .u64 t; cvta.to.shared.u64 t, %1; cvt.u32.u64 %0, t; }" : "=r"(a) : "l"(p));
    return a;
}
__device__ __forceinline__ void mbar_init(uint32_t mbar, uint32_t cnt) {
    asm volatile("mbarrier.init.shared.b64 [%0], %1;" :: "r"(mbar), "r"(cnt) : "memory");
}
__device__ __forceinline__ void mbar_wait(uint32_t mbar, uint32_t parity) {
    asm volatile(
        "{\n\t.reg .pred P;\n\t"
        "WL_%=:\n\t"
        "mbarrier.try_wait.parity.acquire.cta.shared::cta.b64 P, [%0], %1, 0x989680;\n\t"
        "@!P bra WL_%=;\n\t}"
        :: "r"(mbar), "r"(parity) : "memory");
}
#define TMEM_ALLOC(sptr, ncols) \
    asm volatile("tcgen05.alloc.cta_group::1.sync.aligned.shared::cta.b32 [%0], %1;" \
                 :: "r"(sptr), "r"(ncols) : "memory")
#define TMEM_RELINQ() \
    asm volatile("tcgen05.relinquish_alloc_permit.cta_group::1.sync.aligned;")
#define TMEM_DEALLOC(taddr, ncols) \
    asm volatile("tcgen05.dealloc.cta_group::1.sync.aligned.b32 %0, %1;" :: "r"(taddr), "r"(ncols))
#define TC_COMMIT(mbar) \
    asm volatile("tcgen05.commit.cta_group::1.mbarrier::arrive::one.shared::cluster.b64 [%0];" \
                 :: "r"(mbar) : "memory")
#define TC_FENCE_AFTER()  asm volatile("tcgen05.fence::after_thread_sync;" ::: "memory")
#define TC_FENCE_BEFORE() asm volatile("tcgen05.fence::before_thread_sync;" ::: "memory")
#define FENCE_ASYNC_SHARED() asm volatile("fence.proxy.async.shared::cta;" ::: "memory")
#define TC_WAIT_LD() asm volatile("tcgen05.wait::ld.sync.aligned;" ::: "memory")

#define TCGEN05_MMA_F16(d_tmem, a_desc, b_desc, idesc, en) do {                          \
    unsigned _e = (en);                                                                  \
    asm volatile("{\n\t.reg .pred p;\n\tsetp.ne.u32 p, %4, 0;\n\t"                       \
        "tcgen05.mma.cta_group::1.kind::f16 [%0], %1, %2, %3, {%5, %5, %5, %5}, p;\n\t}" \
        :: "r"(d_tmem), "l"(a_desc), "l"(b_desc), "r"(idesc), "r"(_e), "r"(0u)           \
        : "memory");                                                                     \
} while (0)

// 16-register TMEM load (keeps epilogue under the 64-reg cap at occ 4)
#define TC_LD_X16(r, taddr)                                                              \
    asm volatile("tcgen05.ld.sync.aligned.32x32b.x16.b32 "                               \
        "{%0,%1,%2,%3,%4,%5,%6,%7,%8,%9,%10,%11,%12,%13,%14,%15}, [%16];"                \
        : "=r"((r)[0]), "=r"((r)[1]), "=r"((r)[2]), "=r"((r)[3]),                        \
          "=r"((r)[4]), "=r"((r)[5]), "=r"((r)[6]), "=r"((r)[7]),                        \
          "=r"((r)[8]), "=r"((r)[9]), "=r"((r)[10]), "=r"((r)[11]),                      \
          "=r"((r)[12]), "=r"((r)[13]), "=r"((r)[14]), "=r"((r)[15])                     \
        : "r"(taddr))

// SW128 descriptor (proven): LBO=1, SBO=64, layout=2, version=1
static __device__ __forceinline__ uint64_t make_desc128(uint32_t addr) {
    const uint64_t base = (uint64_t(2) << 61) | (uint64_t(1) << 46)
                        | (uint64_t(64) << 32) | (uint64_t(1) << 16);
    return base | ((uint64_t)(addr >> 4) & 0x3FFF);
}
// idesc kind::f16 (fp16 in, fp32 acc): dtype=F32(1)<<4, atype=F16(0), btype=F16(0),
// N/8=8 <<17, M/16=8 <<24  -> M=128, N=64
#define IDESC_F16 0x8100010u
#endif  // HAS_TCGEN05

// tcgen05 smem layout (bytes): two buffers, each A(16K) | B(8K); 52.3KB -> occ 4
#define BUF_STRIDE 24576
#define A_OFF  0
#define B_OFF  16384
#define S_W4   49152
#define S_IX   51200
#define S_TPTR 53248
#define S_MBAR0 53256
#define S_MBAR1 53264
#define SMEM_TC 53280
#define SMEM_FB 103456          // fallback layout size

// ---------------------------------------------------------------------------
// Main kernel: one (b,y) row per block, 256 threads, occupancy 4. Dual-path.
// Gather bilinear now in fp16 HFMA2 (weights pre-packed as dup half2).
// ---------------------------------------------------------------------------
__global__ __launch_bounds__(NT, 4) void deform_main(
    const float* __restrict__ offset,
    const float* __restrict__ bias,
    float* __restrict__ out)
{
    extern __shared__ char smc[];
    const int tid = threadIdx.x;
    const int bid = blockIdx.x;
    const int b = bid >> 7, y = bid & 127;
    const float* offb = offset + (size_t)b * (2 * KK) * HW + (size_t)y * Ww;
    const __half* xh = g_xh + (size_t)b * HW * Cc;

#if HAS_TCGEN05
    // ============ tcgen05 fp16, double-buffered, occ 4 single wave ============
    const uint32_t sbase = smem_u32(smc);
    int* s_ix = (int*)(smc + S_IX);
    const int wid = tid >> 5, lid = tid & 31;

    if (wid == 0) { TMEM_ALLOC(sbase + S_TPTR, 64); TMEM_RELINQ(); }
    if (tid == 0) { mbar_init(sbase + S_MBAR0, 1); mbar_init(sbase + S_MBAR1, 1); }
    __syncthreads();
    uint32_t tmem;
    asm volatile("ld.shared.b32 %0, [%1];" : "=r"(tmem) : "r"(sbase + S_TPTR));

    // offset prefetch (tap 0)
    float oxc = 0.f, oyc = 0.f;
    if (tid < 128) { oxc = offb[tid]; oyc = offb[HW + tid]; }

    int ph0 = 0, ph1 = 0;
    for (int t = 0; t < KK; ++t) {
        const int buf = t & 1;
        const uint32_t bufo = buf * BUF_STRIDE;
        const uint32_t mb = sbase + (buf ? S_MBAR1 : S_MBAR0);
        if (t >= 2) {   // buffer reused: wait for tap t-2's MMAs to complete
            if (buf == 0) { mbar_wait(mb, ph0); ph0 ^= 1; }
            else          { mbar_wait(mb, ph1); ph1 ^= 1; }
        }

        // ---- coords for 128 pixels; prefetch next tap's offsets ----
        if (tid < 128) {
            int xx = tid;
            float oxn = 0.f, oyn = 0.f;
            if (t + 1 < KK) {
                oxn = offb[(size_t)(2 * t + 2) * HW + xx];
                oyn = offb[(size_t)(2 * t + 3) * HW + xx];
            }
            float pxf = (float)xx + oxc, pyf = (float)y + oyc;
            float x0f = floorf(pxf), y0f = floorf(pyf);
            float fx = pxf - x0f, fy = pyf - y0f;
            int x0 = (int)x0f, y0 = (int)y0f;
            int x1 = x0 + 1,   y1 = y0 + 1;
            float vx0 = (x0 >= 0 && x0 < Ww) ? 1.f : 0.f;
            float vx1 = (x1 >= 0 && x1 < Ww) ? 1.f : 0.f;
            float vy0 = (y0 >= 0 && y0 < Hh) ? 1.f : 0.f;
            float vy1 = (y1 >= 0 && y1 < Hh) ? 1.f : 0.f;
            int cx0 = min(max(x0, 0), Ww - 1), cx1 = min(max(x1, 0), Ww - 1);
            int cy0 = min(max(y0, 0), Hh - 1), cy1 = min(max(y1, 0), Hh - 1);
            float w0 = (1.f - fx) * (1.f - fy) * vx0 * vy0;
            float w1 = fx * (1.f - fy) * vx1 * vy0;
            float w2 = (1.f - fx) * fy * vx0 * vy1;
            float w3 = fx * fy * vx1 * vy1;
            // pack as duplicated half2 for HFMA2 gather
            __half2 p0 = __floats2half2_rn(w0, w0);
            __half2 p1 = __floats2half2_rn(w1, w1);
            __half2 p2 = __floats2half2_rn(w2, w2);
            __half2 p3 = __floats2half2_rn(w3, w3);
            ((uint4*)(smc + S_W4))[xx] =
                make_uint4(*(uint32_t*)&p0, *(uint32_t*)&p1,
                           *(uint32_t*)&p2, *(uint32_t*)&p3);
            ((uint4*)s_ix)[xx] = make_uint4((uint32_t)(cy0 * Ww + cx0),
                                            (uint32_t)(cy0 * Ww + cx1),
                                            (uint32_t)(cy1 * Ww + cx0),
                                            (uint32_t)(cy1 * Ww + cx1));
            oxc = oxn; oyc = oyn;
        }
        {   // stage pre-swizzled fp16 B tile: 512 uint4 (2 iters)
            const uint4* sh = g_wh + t * 512;
            uint4* dh = (uint4*)(smc + bufo + B_OFF);
            dh[tid] = sh[tid];
            dh[tid + 256] = sh[tid + 256];
        }
        __syncthreads();

        // ---- gather + HFMA2 bilinear -> fp16 A tile ----
        // tasks: 128 px * 8 groups of 8 channels = 1024 = 4 x 256
        char* aP = smc + bufo + A_OFF;
#pragma unroll
        for (int it = 0; it < 4; ++it) {
            int task = it * NT + tid;
            int gpx = task >> 3, cg = task & 7;
            uint4 wp = ((const uint4*)(smc + S_W4))[gpx];
            uint4 ip = ((const uint4*)s_ix)[gpx];
            __half2 W0 = *(__half2*)&wp.x, W1 = *(__half2*)&wp.y;
            __half2 W2 = *(__half2*)&wp.z, W3 = *(__half2*)&wp.w;
            const int co = cg * 8;
            uint4 q0 = *(const uint4*)(xh + ((size_t)ip.x << 6) + co);
            uint4 q1 = *(const uint4*)(xh + ((size_t)ip.y << 6) + co);
            uint4 q2 = *(const uint4*)(xh + ((size_t)ip.z << 6) + co);
            uint4 q3 = *(const uint4*)(xh + ((size_t)ip.w << 6) + co);
            const __half2* a0 = (const __half2*)&q0;
            const __half2* a1 = (const __half2*)&q1;
            const __half2* a2 = (const __half2*)&q2;
            const __half2* a3 = (const __half2*)&q3;
            uint32_t res[4];
#pragma unroll
            for (int j = 0; j < 4; ++j) {
                __half2 r = __hmul2(W0, a0[j]);
                r = __hfma2(W1, a1[j], r);
                r = __hfma2(W2, a2[j], r);
                r = __hfma2(W3, a3[j], r);
                res[j] = *(uint32_t*)&r;
            }
            uint32_t sw = sw128((uint32_t)(gpx * 128 + cg * 16));
            *(uint4*)(aP + sw) = make_uint4(res[0], res[1], res[2], res[3]);
        }
        TC_FENCE_BEFORE();
        __syncthreads();

        // ---- MMAs: 4 K-chunks, single commit ----
        if (tid == 0) {
            FENCE_ASYNC_SHARED();
            TC_FENCE_AFTER();
            uint64_t aD = make_desc128(sbase + bufo + A_OFF);
            uint64_t bD = make_desc128(sbase + bufo + B_OFF);
#pragma unroll
            for (int q = 0; q < 4; ++q) {        // K chunks of 16 fp16 = +2 units
                uint64_t o2 = (uint64_t)(q * 2);
                TCGEN05_MMA_F16(tmem, aD + o2, bD + o2, IDESC_F16,
                                (t > 0 || q > 0) ? 1u : 0u);
            }
            TC_COMMIT(mb);
        }
    }

    // final commit was tap 8 -> slot 0
    mbar_wait(sbase + S_MBAR0, ph0);
    TC_FENCE_AFTER();

    if (wid < 4) {
        int px = wid * 32 + lid;
        float* outb = out + ((size_t)b * Oo * Hh + y) * Ww + px;
#pragma unroll
        for (int chunk = 0; chunk < 4; ++chunk) {     // 16 cols at a time
            uint32_t r[16];
            TC_LD_X16(r, tmem + chunk * 16);
            TC_WAIT_LD();
#pragma unroll
            for (int j = 0; j < 16; ++j) {
                int o = chunk * 16 + j;
                outb[(size_t)o * HW] = __uint_as_float(r[j]) + __ldg(bias + o);
            }
        }
        TC_FENCE_BEFORE();
    }
    __syncthreads();
    if (wid == 0) TMEM_DEALLOC(tmem, 64);

#else
    // ============ FFMA2 fallback path (fp16 image, 256 thr: 128 cons/128 prod) ============
    float* smem = (float*)smc;
    float* sms  = smem;                        // 2 x [64][SPAD]
    float* smw  = smem + 2 * 64 * SPAD;        // 2 x [64][64]
    float* smw4 = smw + 2 * 64 * 64;           // [128][4]
    int*   smix = (int*)(smw4 + 128 * 4);      // [128][4]

    const bool producer = (tid >= 128);
    const int ptid = tid - 128;
    const int px0 = (tid & 15) * 8;
    const int o0  = (tid >> 4) * 8;

    unsigned long long acc[32];                // 8 px x 4 o-pairs
#pragma unroll
    for (int i = 0; i < 32; ++i) acc[i] = 0ull;

    auto produce = [&](int tt) {
        float* sdst = sms + (tt & 1) * 64 * SPAD;
        {
            int xx = ptid;
            float ox = offb[(size_t)(2 * tt)     * HW + xx];
            float oy = offb[(size_t)(2 * tt + 1) * HW + xx];
            float pxf = (float)xx + ox;
            float pyf = (float)y  + oy;
            float x0f = floorf(pxf), y0f = floorf(pyf);
            float fx = pxf - x0f, fy = pyf - y0f;
            int x0 = (int)x0f, y0 = (int)y0f;
            int x1 = x0 + 1,   y1 = y0 + 1;
            float vx0 = (x0 >= 0 && x0 < Ww) ? 1.f : 0.f;
            float vx1 = (x1 >= 0 && x1 < Ww) ? 1.f : 0.f;
            float vy0 = (y0 >= 0 && y0 < Hh) ? 1.f : 0.f;
            float vy1 = (y1 >= 0 && y1 < Hh) ? 1.f : 0.f;
            int cx0 = min(max(x0, 0), Ww - 1), cx1 = min(max(x1, 0), Ww - 1);
            int cy0 = min(max(y0, 0), Hh - 1), cy1 = min(max(y1, 0), Hh - 1);
            smw4[xx * 4 + 0] = (1.f - fx) * (1.f - fy) * vx0 * vy0;
            smw4[xx * 4 + 1] = fx * (1.f - fy) * vx1 * vy0;
            smw4[xx * 4 + 2] = (1.f - fx) * fy * vx0 * vy1;
            smw4[xx * 4 + 3] = fx * fy * vx1 * vy1;
            smix[xx * 4 + 0] = cy0 * Ww + cx0;
            smix[xx * 4 + 1] = cy0 * Ww + cx1;
            smix[xx * 4 + 2] = cy1 * Ww + cx0;
            smix[xx * 4 + 3] = cy1 * Ww + cx1;
        }
        {
            const float4* wsrc = (const float4*)(g_wt + (size_t)tt * Cc * Oo);
            float4* wdst = (float4*)(smw + (tt & 1) * 64 * 64);
#pragma unroll
            for (int i = 0; i < 8; ++i) wdst[ptid + i * 128] = wsrc[ptid + i * 128];
        }
        asm volatile("bar.sync 1, 128;" ::: "memory");
#pragma unroll 4
        for (int it = 0; it < 16; ++it) {
            int task = it * 128 + ptid;
            int gpx = task >> 4, cg = task & 15;
            float w0 = smw4[gpx * 4 + 0], w1 = smw4[gpx * 4 + 1];
            float w2 = smw4[gpx * 4 + 2], w3 = smw4[gpx * 4 + 3];
            int i0 = smix[gpx * 4 + 0], i1 = smix[gpx * 4 + 1];
            int i2 = smix[gpx * 4 + 2], i3 = smix[gpx * 4 + 3];
            const int co = cg * 4;
            uint2 q0 = *(const uint2*)(xh + ((size_t)i0 << 6) + co);
            uint2 q1 = *(const uint2*)(xh + ((size_t)i1 << 6) + co);
            uint2 q2 = *(const uint2*)(xh + ((size_t)i2 << 6) + co);
            uint2 q3 = *(const uint2*)(xh + ((size_t)i3 << 6) + co);
            const __half2* a0 = (const __half2*)&q0;
            const __half2* a1 = (const __half2*)&q1;
            const __half2* a2 = (const __half2*)&q2;
            const __half2* a3 = (const __half2*)&q3;
            float* dc = sdst + (cg * 4) * SPAD + gpx;
#pragma unroll
            for (int j = 0; j < 2; ++j) {
                float2 f0 = __half22float2(a0[j]);
                float2 f1 = __half22float2(a1[j]);
                float2 f2 = __half22float2(a2[j]);
                float2 f3 = __half22float2(a3[j]);
                dc[(2 * j) * SPAD] =
                    fmaf(w3, f3.x, fmaf(w2, f2.x, fmaf(w1, f1.x, w0 * f0.x)));
                dc[(2 * j + 1) * SPAD] =
                    fmaf(w3, f3.y, fmaf(w2, f2.y, fmaf(w1, f1.y, w0 * f0.y)));
            }
        }
    };

    if (producer) produce(0);
    __syncthreads();

    for (int t = 0; t < KK; ++t) {
        if (producer) {
            if (t + 1 < KK) produce(t + 1);
        } else {
            const float* sb = sms + (t & 1) * 64 * SPAD + px0;
            const float* sw = smw + (t & 1) * 64 * 64 + o0;
            for (int c = 0; c < 64; ++c) {
                ulonglong2 wA = *(const ulonglong2*)(sw + c * 64);
                ulonglong2 wB = *(const ulonglong2*)(sw + c * 64 + 4);
#pragma unroll
                for (int i = 0; i < 8; ++i) {
                    float sf = sb[c * SPAD + i];
                    unsigned long long dv;
                    asm("mov.b64 %0, {%1,%1};" : "=l"(dv) : "r"(__float_as_uint(sf)));
                    FMA2(acc[i * 4 + 0], wA.x, dv);
                    FMA2(acc[i * 4 + 1], wA.y, dv);
                    FMA2(acc[i * 4 + 2], wB.x, dv);
                    FMA2(acc[i * 4 + 3], wB.y, dv);
                }
            }
        }
        __syncthreads();
    }

    if (!producer) {
        float* stg = sms;
#pragma unroll
        for (int k = 0; k < 4; ++k) {
            float blo = bias[o0 + 2 * k];
            float bhi = bias[o0 + 2 * k + 1];
#pragma unroll
            for (int i = 0; i < 8; ++i) {
                unsigned long long a = acc[i * 4 + k];
                float lo = __uint_as_float((unsigned)(a & 0xffffffffull));
                float hi = __uint_as_float((unsigned)(a >> 32));
                stg[(o0 + 2 * k) * OSTRIDE + px0 + i]     = lo + blo;
                stg[(o0 + 2 * k + 1) * OSTRIDE + px0 + i] = hi + bhi;
            }
        }
    }
    __syncthreads();
    {
        float* outb = out + ((size_t)b * Oo * Hh + y) * Ww;
        const float* stg = sms;
        for (int idx = tid; idx < Oo * Ww / 4; idx += NT) {
            int o = idx >> 5, q = idx & 31;
            float4 v = *(const float4*)(stg + o * OSTRIDE + q * 4);
            *(float4*)(outb + (size_t)o * HW + q * 4) = v;
        }
    }
#endif
}

extern "C" void kernel_launch(void* const* d_in, const int* in_sizes, int n_in,
                              void* d_out, int out_size) {
    const float* x      = (const float*)d_in[0];
    const float* offset = (const float*)d_in[1];
    const float* weight = (const float*)d_in[2];
    const float* bias   = (const float*)d_in[3];
    float* out = (float*)d_out;

    // fused transpose (1024 blocks) + weight prep (288 blocks)
    prep_kernel<<<1024 + 288, 128>>>(x, weight);

    int dev = 0, major = 0;
    cudaGetDevice(&dev);
    cudaDeviceGetAttribute(&major, cudaDevAttrComputeCapabilityMajor, dev);
    int smem = (major >= 10) ? SMEM_TC : SMEM_FB;   // tcgen05 path vs fallback
    cudaFuncSetAttribute(deform_main, cudaFuncAttributeMaxDynamicSharedMemorySize,
                         SMEM_FB);
    deform_main<<<Bb * Hh, NT, smem>>>(offset, bias, out);
}